// round 2
// baseline (speedup 1.0000x reference)
#include <cuda_runtime.h>
#include <cstdint>

#define TT 32

// ---------------- scratch (device globals: allocation-free) ----------------
static __device__ float g_Apos[(size_t)128 * 1024 * 512];  // [bt][m][512]  256MB
static __device__ float g_A   [(size_t)128 * 1024 * 512];  // [bt][n][512]  256MB
static __device__ float g_out0[(size_t)4 * 32 * 132 * 1024];
static __device__ float g_Hh  [(size_t)4 * 1024 * 512];
static __device__ float g_cb  [2][(size_t)4 * 1024 * 128];
static __device__ int   g_idx [(size_t)4 * 32 * 1024 * 16];
static __device__ float g_wEA0[512 * 4];
static __device__ float g_wEA1[512 * 132];

// ---------------- helpers ----------------
__device__ __forceinline__ void fma2(unsigned long long& acc, unsigned long long a,
                                     unsigned long long b) {
    asm("fma.rn.f32x2 %0, %1, %2, %3;" : "=l"(acc) : "l"(a), "l"(b), "l"(acc));
}
__device__ __forceinline__ unsigned long long dup2(float w) {
    unsigned long long r;
    asm("mov.b64 %0, {%1, %1};" : "=l"(r) : "f"(w));
    return r;
}
__device__ __forceinline__ float tanha(float x) {
    float y;
    asm("tanh.approx.f32 %0, %1;" : "=f"(y) : "f"(x));
    return y;
}
__device__ __forceinline__ float sigm(float x) {
    return fmaf(0.5f, tanha(0.5f * x), 0.5f);  // 1 MUFU instead of 2-3
}

// ---------------- KNN: stable top-16 of d2 = q2 + r2 - 2 q.r ----------------
__global__ __launch_bounds__(256) void knn_kernel(const float* __restrict__ x,
                                                  float* __restrict__ outG,
                                                  int* __restrict__ idxOut) {
    __shared__ float rx[1024], ry[1024], rz[1024], rs[1024];
    int b = blockIdx.z, t = blockIdx.y;
    int n = blockIdx.x * 256 + threadIdx.x;
    int prev = t ? t - 1 : 0;
    const float* rb = x + (size_t)(b * TT + prev) * 4 * 1024;
    for (int i = threadIdx.x; i < 1024; i += 256) {
        float a = rb[i], c = rb[1024 + i], d = rb[2048 + i];
        rx[i] = a; ry[i] = c; rz[i] = d;
        rs[i] = __fadd_rn(__fadd_rn(__fmul_rn(a, a), __fmul_rn(c, c)), __fmul_rn(d, d));
    }
    __syncthreads();
    const float* qb = x + (size_t)(b * TT + t) * 4 * 1024;
    float qx = qb[n], qy = qb[1024 + n], qz = qb[2048 + n];
    float q2 = __fadd_rn(__fadd_rn(__fmul_rn(qx, qx), __fmul_rn(qy, qy)), __fmul_rn(qz, qz));
    float bd[16]; int bi[16];
#pragma unroll
    for (int i = 0; i < 16; i++) { bd[i] = 3.4e38f; bi[i] = 0; }
    for (int m = 0; m < 1024; m++) {
        float qr = fmaf(qz, rz[m], fmaf(qy, ry[m], __fmul_rn(qx, rx[m])));
        float d2 = (q2 + rs[m]) - 2.0f * qr;
        if (d2 < bd[15]) {
            int pos = 0;
#pragma unroll
            for (int i = 0; i < 16; i++) pos += (bd[i] <= d2) ? 1 : 0;  // stable: ties keep rank
#pragma unroll
            for (int i = 15; i > 0; i--)
                if (i > pos) { bd[i] = bd[i - 1]; bi[i] = bi[i - 1]; }
#pragma unroll
            for (int i = 0; i < 16; i++)
                if (i == pos) { bd[i] = d2; bi[i] = m; }
        }
    }
    size_t o = (size_t)((b * TT + t) * 1024 + n) * 16;
#pragma unroll
    for (int k = 0; k < 16; k++) { idxOut[o + k] = bi[k]; outG[o + k] = (float)bi[k]; }
}

// ------- weight prep: fold "-x_t[:4]" (pos adjust) into the A-path weights -------
__global__ void setup_kernel(const float* __restrict__ w0, const float* __restrict__ w1,
                             float* __restrict__ wEA0, float* __restrict__ wEA1) {
    int i = blockIdx.x * 256 + threadIdx.x;
    if (i < 512 * 4) {
        int o = i >> 2, j = i & 3;
        wEA0[i] = w0[o * 136 + j] - w0[o * 136 + 4 + j];
    }
    if (i < 512 * 132) {
        int o = i / 132, c = i % 132;
        float v = w1[o * 264 + c];
        if (c < 4) v -= w1[o * 264 + 132 + c];
        wEA1[i] = v;
    }
}

// ------- copy position channels into both layer-output buffers (ch 0..3 of 132) ---
__global__ void copypos_kernel(const float* __restrict__ x, float* __restrict__ out,
                               float* __restrict__ out0) {
    int i = blockIdx.x * 256 + threadIdx.x;  // 524288 = 4*32*4*1024
    int n = i & 1023;
    int c = (i >> 10) & 3;
    int bt = i >> 12;
    float v = x[i];
    size_t dst = ((size_t)bt * 132 + c) * 1024 + n;
    out[dst] = v;
    out0[dst] = v;
}

// ---- generic GEMM: Out[z][m][o] = bias[o] + Init_z[m][o] + sum_j W[o][j]*In_zi[j][m]
// BM=128, BN=64, BK=16, 256 threads, packed f32x2 FMA (2 m-rows per instr)
__global__ __launch_bounds__(256) void gemm_kernel(
    const float* __restrict__ In0, long inZ, int prevFlag,
    const float* __restrict__ W, int ldw, int Kdim,
    const float* __restrict__ bias,
    const float* __restrict__ Init0, long initZ,
    float* __restrict__ Out0, long outZ) {
    __shared__ float sIn[16][128];
    __shared__ float sW[16][65];
    int z = blockIdx.z;
    int zi = z;
    if (prevFlag) { int bb = z >> 5, tt = z & 31; zi = (bb << 5) + (tt ? tt - 1 : 0); }
    const float* In = In0 + (size_t)zi * inZ;
    float* Out = Out0 + (size_t)z * outZ;
    int mTile = blockIdx.x * 128;
    int oTile = blockIdx.y * 64;
    int tid = threadIdx.x;
    int tx = tid & 15, ty = tid >> 4;
    unsigned long long acc[4][4];
#pragma unroll
    for (int a = 0; a < 4; a++)
#pragma unroll
        for (int c = 0; c < 4; c++) acc[a][c] = 0ULL;
    int nkt = (Kdim + 15) >> 4;
    for (int kt = 0; kt < nkt; kt++) {
        int k0 = kt << 4;
        for (int i = tid; i < 2048; i += 256) {
            int j = i >> 7, mm = i & 127;
            sIn[j][mm] = (k0 + j < Kdim) ? In[(size_t)(k0 + j) * 1024 + mTile + mm] : 0.f;
        }
        for (int i = tid; i < 1024; i += 256) {
            int j = i & 15, o = i >> 4;
            sW[j][o] = (k0 + j < Kdim) ? W[(size_t)(oTile + o) * ldw + k0 + j] : 0.f;
        }
        __syncthreads();
#pragma unroll
        for (int j = 0; j < 16; j++) {
            unsigned long long iv[4], wv[4];
#pragma unroll
            for (int s = 0; s < 4; s++)
                iv[s] = *reinterpret_cast<const unsigned long long*>(&sIn[j][ty * 2 + 32 * s]);
#pragma unroll
            for (int s = 0; s < 4; s++) wv[s] = dup2(sW[j][tx + 16 * s]);
#pragma unroll
            for (int mi = 0; mi < 4; mi++)
#pragma unroll
                for (int oi = 0; oi < 4; oi++) fma2(acc[mi][oi], iv[mi], wv[oi]);
        }
        __syncthreads();
    }
#pragma unroll
    for (int mi = 0; mi < 4; mi++) {
        int m = mTile + ty * 2 + 32 * mi;
#pragma unroll
        for (int oi = 0; oi < 4; oi++) {
            int o = oTile + tx + 16 * oi;
            float lo, hi;
            asm("mov.b64 {%0, %1}, %2;" : "=f"(lo), "=f"(hi) : "l"(acc[mi][oi]));
            float add = bias ? bias[o] : 0.f;
            size_t p0 = (size_t)m * 512 + o;
            float i0 = 0.f, i1 = 0.f;
            if (Init0) {
                const float* Init = Init0 + (size_t)z * initZ;
                i0 = Init[p0];
                i1 = Init[p0 + 512];
            }
            Out[p0] = lo + add + i0;
            Out[p0 + 512] = hi + add + i1;
        }
    }
}

// ------- step B: gather gates, LSTM nonlinearity, max over k, transpose h out -----
__global__ __launch_bounds__(256) void stepB_kernel(
    const float* __restrict__ A_t, const float* __restrict__ Hh0, long hhB,
    const int* __restrict__ idx_t, const float* __restrict__ cPrev,
    float* __restrict__ hOut0, long hOutB, float* __restrict__ cOut, int t0) {
    int b = blockIdx.y;
    int warp = threadIdx.x >> 5, lane = threadIdx.x & 31;
    int n = blockIdx.x * 8 + warp;
    const float* A = A_t + (size_t)b * (TT * 1024 * 512) + (size_t)n * 512;
    const float* Hh = Hh0 + (size_t)b * hhB;
    const int* idx = idx_t + (size_t)b * (TT * 1024 * 16) + n * 16;
    const float* cp = cPrev + (size_t)b * (1024 * 128);
    float Ai[4], Af[4], Ao[4], Ag[4], hm[4], cm[4];
#pragma unroll
    for (int j = 0; j < 4; j++) {
        int d = j * 32 + lane;
        Ai[j] = A[d];
        Af[j] = A[128 + d];
        Ao[j] = A[256 + d];
        Ag[j] = A[384 + d];
        hm[j] = -3.4e38f;
        cm[j] = -3.4e38f;
    }
    for (int k = 0; k < 16; k++) {
        int m = idx[k];
        const float* Hr = Hh + (size_t)m * 512;
        const float* cr = cp + (size_t)m * 128;
#pragma unroll
        for (int j = 0; j < 4; j++) {
            int d = j * 32 + lane;
            float gi = Ai[j] + Hr[d];
            float gf = Af[j] + Hr[128 + d];
            float go = Ao[j] + Hr[256 + d];
            float gg = Ag[j] + Hr[384 + d];
            float cgv = t0 ? 0.f : cr[d];
            float cn = sigm(gf) * cgv + sigm(gi) * tanha(gg);
            float hn = sigm(go) * tanha(cn);
            cm[j] = fmaxf(cm[j], cn);
            hm[j] = fmaxf(hm[j], hn);
        }
    }
    float* co = cOut + (size_t)(b * 1024 + n) * 128;
#pragma unroll
    for (int j = 0; j < 4; j++) co[j * 32 + lane] = cm[j];
    __shared__ float sh[128][9];
#pragma unroll
    for (int j = 0; j < 4; j++) sh[j * 32 + lane][warp] = hm[j];
    __syncthreads();
    float* ho = hOut0 + (size_t)b * hOutB;
    int n0 = blockIdx.x * 8;
    for (int i = threadIdx.x; i < 1024; i += 256) {
        int d = i >> 3, nn = i & 7;
        ho[(size_t)d * 1024 + n0 + nn] = sh[d][nn];
    }
}

// ------- final: h copy from out1[t=31], c transpose [b][n][d] -> [b][d][n] --------
__global__ void final_kernel(float* __restrict__ out, const float* __restrict__ cfin) {
    int i = blockIdx.x * 256 + threadIdx.x;  // 524288 = 4*128*1024
    int b = i >> 17;
    int r = i & 131071;
    int d = r >> 10;
    int n = r & 1023;
    out[17301504 + i] = out[((size_t)((b * 32 + 31) * 132) + 4 + d) * 1024 + n];
    out[17825792 + i] = cfin[(size_t)(b * 1024 + n) * 128 + d];
}

// ---------------- launch ----------------
extern "C" void kernel_launch(void* const* d_in, const int* in_sizes, int n_in,
                              void* d_out, int out_size) {
    const float* x = (const float*)d_in[0];
    const float* w0 = (const float*)d_in[1];
    const float* b0 = (const float*)d_in[2];
    const float* w1 = (const float*)d_in[3];
    const float* b1 = (const float*)d_in[4];
    float* out = (float*)d_out;

    float *Apos, *A, *out0, *Hh, *cb, *wEA0, *wEA1;
    int* idxp;
    cudaGetSymbolAddress((void**)&Apos, g_Apos);
    cudaGetSymbolAddress((void**)&A, g_A);
    cudaGetSymbolAddress((void**)&out0, g_out0);
    cudaGetSymbolAddress((void**)&Hh, g_Hh);
    cudaGetSymbolAddress((void**)&cb, g_cb);
    cudaGetSymbolAddress((void**)&wEA0, g_wEA0);
    cudaGetSymbolAddress((void**)&wEA1, g_wEA1);
    cudaGetSymbolAddress((void**)&idxp, g_idx);

    const long Z = 1024L * 512;         // per-(b,t) A/Hh slab
    const long CS = 4L * 1024 * 128;    // c double-buffer slab

    knn_kernel<<<dim3(4, 32, 4), 256>>>(x, out + 18350080, idxp);
    setup_kernel<<<264, 256>>>(w0, w1, wEA0, wEA1);
    copypos_kernel<<<2048, 256>>>(x, out, out0);

    // ---- layer 0 hoisted GEMMs: A0 (K=4, folded) and Hh_pos0 (K=4, pos_past) ----
    gemm_kernel<<<dim3(8, 8, 128), 256>>>(x, 4096L, 0, wEA0, 4, 4, b0,
                                          nullptr, 0L, A, Z);
    gemm_kernel<<<dim3(8, 8, 128), 256>>>(x, 4096L, 1, w0 + 4, 136, 4, nullptr,
                                          nullptr, 0L, Apos, Z);

    for (int t = 0; t < 32; t++) {
        const float* HhP;
        long hhB;
        if (t == 0) { HhP = Apos; hhB = 32L * Z; }
        else {
            gemm_kernel<<<dim3(8, 8, 4), 256>>>(
                out0 + ((size_t)(t - 1) * 132 + 4) * 1024, 32L * 132 * 1024, 0,
                w0 + 8, 136, 128, nullptr, Apos + (size_t)t * Z, 32L * Z, Hh, Z);
            HhP = Hh; hhB = Z;
        }
        stepB_kernel<<<dim3(128, 4), 256>>>(
            A + (size_t)t * Z, HhP, hhB, idxp + t * 16384, cb + (t & 1) * CS,
            out0 + ((size_t)t * 132 + 4) * 1024, 32L * 132 * 1024,
            cb + ((t + 1) & 1) * CS, t == 0);
    }

    // ---- layer 1 hoisted GEMMs: A1 (K=132, folded, input=out0) and Hh_pos1 ----
    gemm_kernel<<<dim3(8, 8, 128), 256>>>(out0, 132L * 1024, 0, wEA1, 132, 132, b1,
                                          nullptr, 0L, A, Z);
    gemm_kernel<<<dim3(8, 8, 128), 256>>>(x, 4096L, 1, w1 + 132, 264, 4, nullptr,
                                          nullptr, 0L, Apos, Z);

    for (int t = 0; t < 32; t++) {
        const float* HhP;
        long hhB;
        if (t == 0) { HhP = Apos; hhB = 32L * Z; }
        else {
            gemm_kernel<<<dim3(8, 8, 4), 256>>>(
                out + ((size_t)(t - 1) * 132 + 4) * 1024, 32L * 132 * 1024, 0,
                w1 + 136, 264, 128, nullptr, Apos + (size_t)t * Z, 32L * Z, Hh, Z);
            HhP = Hh; hhB = Z;
        }
        stepB_kernel<<<dim3(128, 4), 256>>>(
            A + (size_t)t * Z, HhP, hhB, idxp + t * 16384, cb + (t & 1) * CS,
            out + ((size_t)t * 132 + 4) * 1024, 32L * 132 * 1024,
            cb + ((t + 1) & 1) * CS, t == 0);
    }

    final_kernel<<<2048, 256>>>(out, cb + 0 * CS);
}